// round 2
// baseline (speedup 1.0000x reference)
#include <cuda_runtime.h>
#include <cstddef>

#define B_    2
#define S_    2048
#define HID_  1024
#define NH_   16
#define HD_   64
#define M_    (B_*S_)          // 4096 rows

// ---------------- scratch (device globals; no allocations allowed) ----------
__device__ float g_Q[(size_t)B_*NH_*S_*HD_];   // [b,h,s,d]
__device__ float g_K[(size_t)B_*NH_*S_*HD_];
__device__ float g_V[(size_t)B_*NH_*S_*HD_];
__device__ float g_X[(size_t)M_*HID_];         // attn out re-merged [b,s,hid]

// ---------------- SGEMM-NT: C[m,n] = sum_k A[m,k] * W[n,k] ------------------
// MODE 0: scatter into head layout [b,h,s,d]   MODE 1: plain + bias -> d_out
template<int MODE>
__global__ __launch_bounds__(256)
void sgemm_nt(const float* __restrict__ A, const float* __restrict__ W,
              const float* __restrict__ bias, float* __restrict__ dst)
{
    __shared__ float As[16][132];
    __shared__ float Bs[16][132];
    const int tid = threadIdx.x;
    const int tx = tid & 15, ty = tid >> 4;          // 16 x 16 thread grid
    const int m0 = blockIdx.y * 128, n0 = blockIdx.x * 128;

    float acc[8][8];
    #pragma unroll
    for (int i = 0; i < 8; i++)
        #pragma unroll
        for (int j = 0; j < 8; j++) acc[i][j] = 0.f;

    for (int k0 = 0; k0 < HID_; k0 += 16) {
        #pragma unroll
        for (int l = 0; l < 2; l++) {
            int idx = tid + l * 256;                 // 0..511 float4 slots
            int r = idx >> 2, c4 = (idx & 3) * 4;
            float4 va = *(const float4*)(A + (size_t)(m0 + r) * HID_ + k0 + c4);
            As[c4+0][r] = va.x; As[c4+1][r] = va.y; As[c4+2][r] = va.z; As[c4+3][r] = va.w;
            float4 vb = *(const float4*)(W + (size_t)(n0 + r) * HID_ + k0 + c4);
            Bs[c4+0][r] = vb.x; Bs[c4+1][r] = vb.y; Bs[c4+2][r] = vb.z; Bs[c4+3][r] = vb.w;
        }
        __syncthreads();
        #pragma unroll
        for (int k = 0; k < 16; k++) {
            float4 a0 = *(const float4*)&As[k][ty*8];
            float4 a1 = *(const float4*)&As[k][ty*8 + 4];
            float4 b0 = *(const float4*)&Bs[k][tx*8];
            float4 b1 = *(const float4*)&Bs[k][tx*8 + 4];
            float ra[8] = {a0.x,a0.y,a0.z,a0.w,a1.x,a1.y,a1.z,a1.w};
            float rb[8] = {b0.x,b0.y,b0.z,b0.w,b1.x,b1.y,b1.z,b1.w};
            #pragma unroll
            for (int i = 0; i < 8; i++)
                #pragma unroll
                for (int j = 0; j < 8; j++)
                    acc[i][j] += ra[i] * rb[j];
        }
        __syncthreads();
    }

    #pragma unroll
    for (int i = 0; i < 8; i++) {
        int m = m0 + ty*8 + i;
        #pragma unroll
        for (int j = 0; j < 8; j++) {
            int c = n0 + tx*8 + j;
            if (MODE == 0) {
                int b = m >> 11, s = m & (S_ - 1);
                int h = c >> 6,  d = c & 63;
                dst[(((size_t)(b * NH_ + h)) * S_ + s) * HD_ + d] = acc[i][j];
            } else {
                dst[(size_t)m * HID_ + c] = acc[i][j] + bias[c];
            }
        }
    }
}

// ---------------- fused causal flash attention ------------------------------
// grid: (S/64 q-tiles, B*NH heads), 256 threads.
// Br=64 q-rows per CTA, Bc=32 k-rows per inner tile. All smem static (<48KB).
__global__ __launch_bounds__(256)
void attn_fused()
{
    __shared__ float Qs[64*68];      // Q tile [64][68]
    __shared__ float Ks[32*68];      // K tile [32][68]; reused as P [64][33]
    __shared__ float Vs[32*68];      // V tile [32][68]
    __shared__ float red[64*17];     // row-reduction scratch
    __shared__ float mrow[64], lrow[64], arow[64];

    const int tid = threadIdx.x;
    const int tx = tid & 15, ty = tid >> 4;       // 16 x 16
    const int qt = blockIdx.x;
    const int bh = blockIdx.y;
    const int q0 = qt * 64;
    const float* Qg = g_Q + (size_t)bh * S_ * HD_;
    const float* Kg = g_K + (size_t)bh * S_ * HD_;
    const float* Vg = g_V + (size_t)bh * S_ * HD_;

    #pragma unroll
    for (int l = 0; l < 4; l++) {
        int idx = tid + l * 256;                  // 1024 float4 slots
        int r = idx >> 4, c4 = (idx & 15) * 4;
        *(float4*)&Qs[r*68 + c4] = *(const float4*)(Qg + (size_t)(q0 + r) * HD_ + c4);
    }
    if (tid < 64) { mrow[tid] = -1e30f; lrow[tid] = 0.f; }

    float acc[4][4];                 // O accum: rows ty*4.., cols tx*4..
    #pragma unroll
    for (int i = 0; i < 4; i++)
        #pragma unroll
        for (int j = 0; j < 4; j++) acc[i][j] = 0.f;
    __syncthreads();

    const int nkt = 2 * qt + 2;                    // 32-row k-subtiles
    for (int kt = 0; kt < nkt; kt++) {
        const int k0 = kt * 32;
        #pragma unroll
        for (int l = 0; l < 2; l++) {
            int idx = tid + l * 256;              // 512 float4 slots per tile
            int r = idx >> 4, c4 = (idx & 15) * 4;
            *(float4*)&Ks[r*68 + c4] = *(const float4*)(Kg + (size_t)(k0 + r) * HD_ + c4);
            *(float4*)&Vs[r*68 + c4] = *(const float4*)(Vg + (size_t)(k0 + r) * HD_ + c4);
        }
        __syncthreads();

        // scores 64x32: s[i][j] = Q[ty*4+i] . K[tx*2+j]
        float s[4][2];
        #pragma unroll
        for (int i = 0; i < 4; i++) { s[i][0] = 0.f; s[i][1] = 0.f; }
        #pragma unroll
        for (int d4 = 0; d4 < 64; d4 += 4) {
            float4 qv[4], kv[2];
            #pragma unroll
            for (int i = 0; i < 4; i++) qv[i] = *(const float4*)&Qs[(ty*4 + i)*68 + d4];
            #pragma unroll
            for (int j = 0; j < 2; j++) kv[j] = *(const float4*)&Ks[(tx*2 + j)*68 + d4];
            #pragma unroll
            for (int i = 0; i < 4; i++)
                #pragma unroll
                for (int j = 0; j < 2; j++)
                    s[i][j] += qv[i].x*kv[j].x + qv[i].y*kv[j].y
                             + qv[i].z*kv[j].z + qv[i].w*kv[j].w;
        }

        // scale + causal mask (only possible in last two subtiles) + row max
        const bool band = (kt >= 2 * qt);
        #pragma unroll
        for (int i = 0; i < 4; i++) {
            int r = ty*4 + i;
            float tm = -1e30f;
            #pragma unroll
            for (int j = 0; j < 2; j++) {
                s[i][j] *= 0.125f;                        // 1/sqrt(64)
                if (band && (k0 + tx*2 + j) > (q0 + r)) s[i][j] = -1e30f;
                tm = fmaxf(tm, s[i][j]);
            }
            red[r*17 + tx] = tm;
        }
        __syncthreads();
        if (tid < 64) {
            float mt = red[tid*17];
            #pragma unroll
            for (int t = 1; t < 16; t++) mt = fmaxf(mt, red[tid*17 + t]);
            float mnew = fmaxf(mrow[tid], mt);
            float a = __expf(mrow[tid] - mnew);
            mrow[tid] = mnew; arow[tid] = a; lrow[tid] *= a;
        }
        __syncthreads();

        // P = exp(s - m) -> stage into Ks buffer as P[64][33]; rescale O
        #pragma unroll
        for (int i = 0; i < 4; i++) {
            int r = ty*4 + i;
            float mr = mrow[r], a = arow[r];
            float ps = 0.f;
            #pragma unroll
            for (int j = 0; j < 2; j++) {
                float p = __expf(s[i][j] - mr);
                Ks[r*33 + tx*2 + j] = p;
                ps += p;
            }
            #pragma unroll
            for (int j = 0; j < 4; j++) acc[i][j] *= a;
            red[r*17 + tx] = ps;
        }
        __syncthreads();
        if (tid < 64) {
            float st = 0.f;
            #pragma unroll
            for (int t = 0; t < 16; t++) st += red[tid*17 + t];
            lrow[tid] += st;
        }

        // O += P @ V : O cols tx*4..tx*4+3
        #pragma unroll 8
        for (int c = 0; c < 32; c++) {
            float4 vv = *(const float4*)&Vs[c*68 + tx*4];
            #pragma unroll
            for (int i = 0; i < 4; i++) {
                float p = Ks[(ty*4 + i)*33 + c];
                acc[i][0] += p * vv.x; acc[i][1] += p * vv.y;
                acc[i][2] += p * vv.z; acc[i][3] += p * vv.w;
            }
        }
        __syncthreads();
    }

    const int b = bh >> 4, h = bh & 15;
    #pragma unroll
    for (int i = 0; i < 4; i++) {
        int r = ty*4 + i;
        float inv = 1.f / lrow[r];
        float4 o;
        o.x = acc[i][0] * inv; o.y = acc[i][1] * inv;
        o.z = acc[i][2] * inv; o.w = acc[i][3] * inv;
        *(float4*)&g_X[((size_t)b * S_ + q0 + r) * HID_ + h * HD_ + tx*4] = o;
    }
}

// ---------------- launch -----------------------------------------------------
extern "C" void kernel_launch(void* const* d_in, const int* in_sizes, int n_in,
                              void* d_out, int out_size)
{
    const float* query = (const float*)d_in[0];
    const float* key   = (const float*)d_in[1];
    const float* value = (const float*)d_in[2];
    // d_in[3] = mask: known causal tril, applied analytically in-kernel
    const float* Wq = (const float*)d_in[4];
    const float* Wk = (const float*)d_in[5];
    const float* Wv = (const float*)d_in[6];
    const float* Wo = (const float*)d_in[7];
    const float* bo = (const float*)d_in[8];
    float* out = (float*)d_out;

    float *Qp, *Kp, *Vp, *Xp;
    cudaGetSymbolAddress((void**)&Qp, g_Q);
    cudaGetSymbolAddress((void**)&Kp, g_K);
    cudaGetSymbolAddress((void**)&Vp, g_V);
    cudaGetSymbolAddress((void**)&Xp, g_X);

    dim3 gg(HID_/128, M_/128);   // (8, 32)
    sgemm_nt<0><<<gg, 256>>>(query, Wq, nullptr, Qp);
    sgemm_nt<0><<<gg, 256>>>(key,   Wk, nullptr, Kp);
    sgemm_nt<0><<<gg, 256>>>(value, Wv, nullptr, Vp);
    attn_fused<<<dim3(S_/64, B_*NH_), 256>>>();
    sgemm_nt<1><<<gg, 256>>>(Xp, Wo, bo, out);
}

// round 7
// speedup vs baseline: 1.4050x; 1.4050x over previous
#include <cuda_runtime.h>
#include <cuda_bf16.h>
#include <cstdint>
#include <cstddef>

#define B_    2
#define S_    2048
#define HID_  1024
#define NH_   16
#define HD_   64
#define M_    (B_*S_)          // 4096 rows

// ---------------- scratch (device globals; no allocations allowed) ----------
__device__ float g_Q[(size_t)B_*NH_*S_*HD_];   // [b,h,s,d]
__device__ float g_K[(size_t)B_*NH_*S_*HD_];
__device__ float g_V[(size_t)B_*NH_*S_*HD_];
__device__ float g_X[(size_t)M_*HID_];         // attn out re-merged [b,s,hid]
__device__ __nv_bfloat16 g_Ah[(size_t)M_*HID_];   // activation split hi
__device__ __nv_bfloat16 g_Al[(size_t)M_*HID_];   // activation split lo
__device__ __nv_bfloat16 g_Wh[(size_t)HID_*HID_]; // weight split hi
__device__ __nv_bfloat16 g_Wl[(size_t)HID_*HID_]; // weight split lo

// ================= generic PTX helpers (sm_80+, no tcgen05) ==================
__device__ __forceinline__ uint32_t smem_u32(const void* p) {
    uint32_t a;
    asm("{ .reg .u64 t; cvta.to.shared.u64 t, %1; cvt.u32.u64 %0, t; }" : "=r"(a) : "l"(p));
    return a;
}
__device__ __forceinline__ void ldsm_x4(uint32_t& r0, uint32_t& r1,
                                        uint32_t& r2, uint32_t& r3, uint32_t addr) {
    asm volatile("ldmatrix.sync.aligned.m8n8.x4.shared.b16 {%0,%1,%2,%3}, [%4];"
                 : "=r"(r0), "=r"(r1), "=r"(r2), "=r"(r3) : "r"(addr));
}
__device__ __forceinline__ void mma_bf16(float* d, const uint32_t* a, const uint32_t* b) {
    asm volatile("mma.sync.aligned.m16n8k16.row.col.f32.bf16.bf16.f32 "
        "{%0,%1,%2,%3}, {%4,%5,%6,%7}, {%8,%9}, {%0,%1,%2,%3};"
        : "+f"(d[0]), "+f"(d[1]), "+f"(d[2]), "+f"(d[3])
        : "r"(a[0]), "r"(a[1]), "r"(a[2]), "r"(a[3]), "r"(b[0]), "r"(b[1]));
}

// ---------------- fp32 -> (bf16 hi, bf16 lo) split ---------------------------
__global__ __launch_bounds__(256)
void split_f32(const float4* __restrict__ x, __nv_bfloat16* __restrict__ hi,
               __nv_bfloat16* __restrict__ lo, int n4)
{
    int i = blockIdx.x * 256 + threadIdx.x;
    if (i >= n4) return;
    float4 v = x[i];
    float vv[4] = {v.x, v.y, v.z, v.w};
    __nv_bfloat16 h[4], l[4];
    #pragma unroll
    for (int j = 0; j < 4; j++) {
        h[j] = __float2bfloat16_rn(vv[j]);
        l[j] = __float2bfloat16_rn(vv[j] - __bfloat162float(h[j]));
    }
    __nv_bfloat162* h2 = (__nv_bfloat162*)hi;
    __nv_bfloat162* l2 = (__nv_bfloat162*)lo;
    h2[2*i]   = __halves2bfloat162(h[0], h[1]);
    h2[2*i+1] = __halves2bfloat162(h[2], h[3]);
    l2[2*i]   = __halves2bfloat162(l[0], l[1]);
    l2[2*i+1] = __halves2bfloat162(l[2], l[3]);
}

// ---------------- split-bf16 mma.sync GEMM-NT --------------------------------
// C[m,n] = sum_k A[m,k]*W[n,k];  C ~= AhWh + AhWl + AlWh  (fp32 accum)
// CTA 128x128, 8 warps (2m x 4n), warp tile 64x32. K chunks of 32.
// MODE 0: scatter into head layout [b,h,s,d];  MODE 1: plain + bias -> d_out
#define RS 40    // smem row stride in bf16 elems (32 data + 8 pad = 80 B)

template<int MODE>
__global__ __launch_bounds__(256, 2)
void mma_gemm(const __nv_bfloat16* __restrict__ Ah, const __nv_bfloat16* __restrict__ Al,
              const __nv_bfloat16* __restrict__ Wh, const __nv_bfloat16* __restrict__ Wl,
              const float* __restrict__ bias, float* __restrict__ dst)
{
    __shared__ __align__(16) __nv_bfloat16 sAh[128*RS], sAl[128*RS];
    __shared__ __align__(16) __nv_bfloat16 sWh[128*RS], sWl[128*RS];
    const int tid = threadIdx.x, lane = tid & 31, wid = tid >> 5;
    const int wm = wid >> 2, wn = wid & 3;            // warp grid 2 x 4
    const int m0 = blockIdx.y * 128, n0 = blockIdx.x * 128;

    float acc[4][4][4];
    #pragma unroll
    for (int f = 0; f < 4; f++)
        #pragma unroll
        for (int g = 0; g < 4; g++)
            #pragma unroll
            for (int e = 0; e < 4; e++) acc[f][g][e] = 0.f;

    // ldmatrix per-lane address patterns
    const int arow  = (lane & 7) + ((lane >> 3) & 1) * 8;  // A: mats 0/1 rows, 2/3 rows
    const int acolB = (lane >> 4) * 16;                    // A: mats 2/3 get +16B (k+8)
    const int brow  = (lane & 7) + (lane >> 4) * 8;        // B: mats 0/1 n0-7, 2/3 n8-15
    const int bcolB = ((lane >> 3) & 1) * 16;              // B: mats 1/3 get +16B (k+8)

    const uint32_t bAh = smem_u32(sAh), bAl = smem_u32(sAl);
    const uint32_t bWh = smem_u32(sWh), bWl = smem_u32(sWl);

    // global load slots: 2 x uint4 per tile per thread
    const int lr0 = tid >> 2;            // rows 0..63
    const int lq  = (tid & 3) * 8;       // elem col 0,8,16,24

    for (int kc = 0; kc < HID_ / 32; kc++) {
        const int k0 = kc * 32;
        #pragma unroll
        for (int i = 0; i < 2; i++) {
            const int r = lr0 + i * 64;
            const int so = r * RS + lq;
            const size_t ga = (size_t)(m0 + r) * HID_ + k0 + lq;
            const size_t gw = (size_t)(n0 + r) * HID_ + k0 + lq;
            *(uint4*)&sAh[so] = *(const uint4*)(Ah + ga);
            *(uint4*)&sAl[so] = *(const uint4*)(Al + ga);
            *(uint4*)&sWh[so] = *(const uint4*)(Wh + gw);
            *(uint4*)&sWl[so] = *(const uint4*)(Wl + gw);
        }
        __syncthreads();

        #pragma unroll
        for (int ks = 0; ks < 2; ks++) {
            const int kB = ks * 32;                    // byte offset of k-step
            uint32_t wh[4][2], wl[4][2];
            #pragma unroll
            for (int p = 0; p < 2; p++) {
                const uint32_t ro = (uint32_t)(wn*32 + p*16 + brow) * (RS*2) + kB + bcolB;
                ldsm_x4(wh[2*p][0], wh[2*p][1], wh[2*p+1][0], wh[2*p+1][1], bWh + ro);
                ldsm_x4(wl[2*p][0], wl[2*p][1], wl[2*p+1][0], wl[2*p+1][1], bWl + ro);
            }
            #pragma unroll
            for (int f = 0; f < 4; f++) {
                const uint32_t ro = (uint32_t)(wm*64 + f*16 + arow) * (RS*2) + kB + acolB;
                uint32_t ah[4], al[4];
                ldsm_x4(ah[0], ah[1], ah[2], ah[3], bAh + ro);
                ldsm_x4(al[0], al[1], al[2], al[3], bAl + ro);
                #pragma unroll
                for (int g = 0; g < 4; g++) {
                    mma_bf16(acc[f][g], ah, wh[g]);
                    mma_bf16(acc[f][g], ah, wl[g]);
                    mma_bf16(acc[f][g], al, wh[g]);
                }
            }
        }
        __syncthreads();
    }

    // epilogue: C frag layout: (row=lane/4 [+8], col=(lane%4)*2 [+1])
    const int mr = lane >> 2, nc = (lane & 3) * 2;
    #pragma unroll
    for (int f = 0; f < 4; f++) {
        #pragma unroll
        for (int g = 0; g < 4; g++) {
            #pragma unroll
            for (int half = 0; half < 2; half++) {
                const int m = m0 + wm*64 + f*16 + mr + half*8;
                const int n = n0 + wn*32 + g*8 + nc;
                const float v0 = acc[f][g][half*2 + 0];
                const float v1 = acc[f][g][half*2 + 1];
                if (MODE == 0) {
                    const int b = m >> 11, s = m & (S_ - 1);
                    const int h = n >> 6,  d = n & 63;
                    float* p = &dst[(((size_t)(b * NH_ + h)) * S_ + s) * HD_ + d];
                    p[0] = v0; p[1] = v1;
                } else {
                    float* p = &dst[(size_t)m * HID_ + n];
                    p[0] = v0 + bias[n];
                    p[1] = v1 + bias[n + 1];
                }
            }
        }
    }
}

// ---------------- fused causal flash attention (unchanged, fp32) -------------
__global__ __launch_bounds__(256)
void attn_fused()
{
    __shared__ float Qs[64*68];
    __shared__ float Ks[32*68];      // reused as P [64][33]
    __shared__ float Vs[32*68];
    __shared__ float red[64*17];
    __shared__ float mrow[64], lrow[64], arow2[64];

    const int tid = threadIdx.x;
    const int tx = tid & 15, ty = tid >> 4;
    const int qt = blockIdx.x;
    const int bh = blockIdx.y;
    const int q0 = qt * 64;
    const float* Qg = g_Q + (size_t)bh * S_ * HD_;
    const float* Kg = g_K + (size_t)bh * S_ * HD_;
    const float* Vg = g_V + (size_t)bh * S_ * HD_;

    #pragma unroll
    for (int l = 0; l < 4; l++) {
        int idx = tid + l * 256;
        int r = idx >> 4, c4 = (idx & 15) * 4;
        *(float4*)&Qs[r*68 + c4] = *(const float4*)(Qg + (size_t)(q0 + r) * HD_ + c4);
    }
    if (tid < 64) { mrow[tid] = -1e30f; lrow[tid] = 0.f; }

    float acc[4][4];
    #pragma unroll
    for (int i = 0; i < 4; i++)
        #pragma unroll
        for (int j = 0; j < 4; j++) acc[i][j] = 0.f;
    __syncthreads();

    const int nkt = 2 * qt + 2;
    for (int kt = 0; kt < nkt; kt++) {
        const int k0 = kt * 32;
        #pragma unroll
        for (int l = 0; l < 2; l++) {
            int idx = tid + l * 256;
            int r = idx >> 4, c4 = (idx & 15) * 4;
            *(float4*)&Ks[r*68 + c4] = *(const float4*)(Kg + (size_t)(k0 + r) * HD_ + c4);
            *(float4*)&Vs[r*68 + c4] = *(const float4*)(Vg + (size_t)(k0 + r) * HD_ + c4);
        }
        __syncthreads();

        float s[4][2];
        #pragma unroll
        for (int i = 0; i < 4; i++) { s[i][0] = 0.f; s[i][1] = 0.f; }
        #pragma unroll
        for (int d4 = 0; d4 < 64; d4 += 4) {
            float4 qv[4], kv[2];
            #pragma unroll
            for (int i = 0; i < 4; i++) qv[i] = *(const float4*)&Qs[(ty*4 + i)*68 + d4];
            #pragma unroll
            for (int j = 0; j < 2; j++) kv[j] = *(const float4*)&Ks[(tx*2 + j)*68 + d4];
            #pragma unroll
            for (int i = 0; i < 4; i++)
                #pragma unroll
                for (int j = 0; j < 2; j++)
                    s[i][j] += qv[i].x*kv[j].x + qv[i].y*kv[j].y
                             + qv[i].z*kv[j].z + qv[i].w*kv[j].w;
        }

        const bool band = (kt >= 2 * qt);
        #pragma unroll
        for (int i = 0; i < 4; i++) {
            int r = ty*4 + i;
            float tm = -1e30f;
            #pragma unroll
            for (int j = 0; j < 2; j++) {
                s[i][j] *= 0.125f;
                if (band && (k0 + tx*2 + j) > (q0 + r)) s[i][j] = -1e30f;
                tm = fmaxf(tm, s[i][j]);
            }
            red[r*17 + tx] = tm;
        }
        __syncthreads();
        if (tid < 64) {
            float mt = red[tid*17];
            #pragma unroll
            for (int t = 1; t < 16; t++) mt = fmaxf(mt, red[tid*17 + t]);
            float mnew = fmaxf(mrow[tid], mt);
            float a = __expf(mrow[tid] - mnew);
            mrow[tid] = mnew; arow2[tid] = a; lrow[tid] *= a;
        }
        __syncthreads();

        #pragma unroll
        for (int i = 0; i < 4; i++) {
            int r = ty*4 + i;
            float mr = mrow[r], a = arow2[r];
            float ps = 0.f;
            #pragma unroll
            for (int j = 0; j < 2; j++) {
                float p = __expf(s[i][j] - mr);
                Ks[r*33 + tx*2 + j] = p;
                ps += p;
            }
            #pragma unroll
            for (int j = 0; j < 4; j++) acc[i][j] *= a;
            red[r*17 + tx] = ps;
        }
        __syncthreads();
        if (tid < 64) {
            float st = 0.f;
            #pragma unroll
            for (int t = 0; t < 16; t++) st += red[tid*17 + t];
            lrow[tid] += st;
        }

        #pragma unroll 8
        for (int c = 0; c < 32; c++) {
            float4 vv = *(const float4*)&Vs[c*68 + tx*4];
            #pragma unroll
            for (int i = 0; i < 4; i++) {
                float p = Ks[(ty*4 + i)*33 + c];
                acc[i][0] += p * vv.x; acc[i][1] += p * vv.y;
                acc[i][2] += p * vv.z; acc[i][3] += p * vv.w;
            }
        }
        __syncthreads();
    }

    const int b = bh >> 4, h = bh & 15;
    #pragma unroll
    for (int i = 0; i < 4; i++) {
        int r = ty*4 + i;
        float inv = 1.f / lrow[r];
        float4 o;
        o.x = acc[i][0] * inv; o.y = acc[i][1] * inv;
        o.z = acc[i][2] * inv; o.w = acc[i][3] * inv;
        *(float4*)&g_X[((size_t)b * S_ + q0 + r) * HID_ + h * HD_ + tx*4] = o;
    }
}

// ---------------- launch -----------------------------------------------------
extern "C" void kernel_launch(void* const* d_in, const int* in_sizes, int n_in,
                              void* d_out, int out_size)
{
    const float* query = (const float*)d_in[0];
    const float* key   = (const float*)d_in[1];
    const float* value = (const float*)d_in[2];
    // d_in[3] = mask: known causal tril, applied analytically in-kernel
    const float* Wq = (const float*)d_in[4];
    const float* Wk = (const float*)d_in[5];
    const float* Wv = (const float*)d_in[6];
    const float* Wo = (const float*)d_in[7];
    const float* bo = (const float*)d_in[8];
    float* out = (float*)d_out;

    float *Qp, *Kp, *Vp, *Xp;
    __nv_bfloat16 *Ah, *Al, *Wh, *Wl;
    cudaGetSymbolAddress((void**)&Qp, g_Q);
    cudaGetSymbolAddress((void**)&Kp, g_K);
    cudaGetSymbolAddress((void**)&Vp, g_V);
    cudaGetSymbolAddress((void**)&Xp, g_X);
    cudaGetSymbolAddress((void**)&Ah, g_Ah);
    cudaGetSymbolAddress((void**)&Al, g_Al);
    cudaGetSymbolAddress((void**)&Wh, g_Wh);
    cudaGetSymbolAddress((void**)&Wl, g_Wl);

    const int nA4 = M_ * HID_ / 4;     // 1048576
    const int nW4 = HID_ * HID_ / 4;   // 262144
    dim3 gg(HID_/128, M_/128);         // (8, 32)

    split_f32<<<nA4/256, 256>>>((const float4*)query, Ah, Al, nA4);
    split_f32<<<nW4/256, 256>>>((const float4*)Wq, Wh, Wl, nW4);
    mma_gemm<0><<<gg, 256>>>(Ah, Al, Wh, Wl, nullptr, Qp);

    split_f32<<<nA4/256, 256>>>((const float4*)key, Ah, Al, nA4);
    split_f32<<<nW4/256, 256>>>((const float4*)Wk, Wh, Wl, nW4);
    mma_gemm<0><<<gg, 256>>>(Ah, Al, Wh, Wl, nullptr, Kp);

    split_f32<<<nA4/256, 256>>>((const float4*)value, Ah, Al, nA4);
    split_f32<<<nW4/256, 256>>>((const float4*)Wv, Wh, Wl, nW4);
    mma_gemm<0><<<gg, 256>>>(Ah, Al, Wh, Wl, nullptr, Vp);

    attn_fused<<<dim3(S_/64, B_*NH_), 256>>>();

    split_f32<<<nA4/256, 256>>>((const float4*)Xp, Ah, Al, nA4);
    split_f32<<<nW4/256, 256>>>((const float4*)Wo, Wh, Wl, nW4);
    mma_gemm<1><<<gg, 256>>>(Ah, Al, Wh, Wl, bo, out);
}

// round 9
// speedup vs baseline: 2.7713x; 1.9725x over previous
#include <cuda_runtime.h>
#include <cuda_bf16.h>
#include <cstdint>
#include <cstddef>

#define B_    2
#define S_    2048
#define HID_  1024
#define NH_   16
#define HD_   64
#define M_    (B_*S_)          // 4096 rows

// ---------------- scratch (device globals; no allocations allowed) ----------
__device__ __nv_bfloat16 g_Ah[(size_t)M_*HID_];   // activation split hi
__device__ __nv_bfloat16 g_Al[(size_t)M_*HID_];   // activation split lo
__device__ __nv_bfloat16 g_Wh[(size_t)HID_*HID_]; // weight split hi
__device__ __nv_bfloat16 g_Wl[(size_t)HID_*HID_]; // weight split lo
__device__ __nv_bfloat16 g_Qh[(size_t)B_*NH_*S_*HD_], g_Ql[(size_t)B_*NH_*S_*HD_];
__device__ __nv_bfloat16 g_Kh[(size_t)B_*NH_*S_*HD_], g_Kl[(size_t)B_*NH_*S_*HD_];
__device__ __nv_bfloat16 g_Vh[(size_t)B_*NH_*S_*HD_], g_Vl[(size_t)B_*NH_*S_*HD_];

// ================= generic PTX helpers (sm_80+) ==============================
__device__ __forceinline__ uint32_t smem_u32(const void* p) {
    uint32_t a;
    asm("{ .reg .u64 t; cvta.to.shared.u64 t, %1; cvt.u32.u64 %0, t; }" : "=r"(a) : "l"(p));
    return a;
}
__device__ __forceinline__ void ldsm_x4(uint32_t& r0, uint32_t& r1,
                                        uint32_t& r2, uint32_t& r3, uint32_t addr) {
    asm volatile("ldmatrix.sync.aligned.m8n8.x4.shared.b16 {%0,%1,%2,%3}, [%4];"
                 : "=r"(r0), "=r"(r1), "=r"(r2), "=r"(r3) : "r"(addr));
}
__device__ __forceinline__ void ldsm_x4_t(uint32_t& r0, uint32_t& r1,
                                          uint32_t& r2, uint32_t& r3, uint32_t addr) {
    asm volatile("ldmatrix.sync.aligned.m8n8.x4.trans.shared.b16 {%0,%1,%2,%3}, [%4];"
                 : "=r"(r0), "=r"(r1), "=r"(r2), "=r"(r3) : "r"(addr));
}
__device__ __forceinline__ void mma_bf16(float* d, const uint32_t* a, const uint32_t* b) {
    asm volatile("mma.sync.aligned.m16n8k16.row.col.f32.bf16.bf16.f32 "
        "{%0,%1,%2,%3}, {%4,%5,%6,%7}, {%8,%9}, {%0,%1,%2,%3};"
        : "+f"(d[0]), "+f"(d[1]), "+f"(d[2]), "+f"(d[3])
        : "r"(a[0]), "r"(a[1]), "r"(a[2]), "r"(a[3]), "r"(b[0]), "r"(b[1]));
}
// fast 2^x for x <= 0 on fma/alu pipes (rel err ~8e-5); avoids the MUFU wall
__device__ __forceinline__ float exp2p(float x) {
    x = fmaxf(x, -126.f);
    float fi = floorf(x);
    float f = x - fi;
    float y = f * 0.69314718056f;
    float p = 1.f + y*(1.f + y*(0.5f + y*(0.16666667f + y*(0.04166667f + y*0.00833333f))));
    int e = (((int)fi) + 127) << 23;
    return p * __int_as_float(e);
}
__device__ __forceinline__ uint32_t pack_hi(float a, float b, float& ra, float& rb) {
    __nv_bfloat16 ha = __float2bfloat16_rn(a), hb = __float2bfloat16_rn(b);
    ra = a - __bfloat162float(ha); rb = b - __bfloat162float(hb);
    __nv_bfloat162 v = __halves2bfloat162(ha, hb);
    return *(uint32_t*)&v;
}
__device__ __forceinline__ uint32_t pack_bf(float a, float b) {
    __nv_bfloat162 v = __halves2bfloat162(__float2bfloat16_rn(a), __float2bfloat16_rn(b));
    return *(uint32_t*)&v;
}

// ---------------- fp32 -> (bf16 hi, bf16 lo) split ---------------------------
__global__ __launch_bounds__(256)
void split_f32(const float4* __restrict__ x, __nv_bfloat16* __restrict__ hi,
               __nv_bfloat16* __restrict__ lo, int n4)
{
    int i = blockIdx.x * 256 + threadIdx.x;
    if (i >= n4) return;
    float4 v = x[i];
    float vv[4] = {v.x, v.y, v.z, v.w};
    __nv_bfloat16 h[4], l[4];
    #pragma unroll
    for (int j = 0; j < 4; j++) {
        h[j] = __float2bfloat16_rn(vv[j]);
        l[j] = __float2bfloat16_rn(vv[j] - __bfloat162float(h[j]));
    }
    __nv_bfloat162* h2 = (__nv_bfloat162*)hi;
    __nv_bfloat162* l2 = (__nv_bfloat162*)lo;
    h2[2*i]   = __halves2bfloat162(h[0], h[1]);
    h2[2*i+1] = __halves2bfloat162(h[2], h[3]);
    l2[2*i]   = __halves2bfloat162(l[0], l[1]);
    l2[2*i+1] = __halves2bfloat162(l[2], l[3]);
}

// ---------------- split-bf16 mma.sync GEMM-NT --------------------------------
// C[m,n] = sum_k A[m,k]*W[n,k];  C ~= AhWh + AhWl + AlWh  (fp32 accum)
// MODE 0: split-write into head layout [b,h,s,d] (dstH/dstL bf16)
// MODE 1: fp32 + bias -> dstF
#define RS 40

template<int MODE>
__global__ __launch_bounds__(256, 2)
void mma_gemm(const __nv_bfloat16* __restrict__ Ah, const __nv_bfloat16* __restrict__ Al,
              const __nv_bfloat16* __restrict__ Wh, const __nv_bfloat16* __restrict__ Wl,
              const float* __restrict__ bias, float* __restrict__ dstF,
              __nv_bfloat16* __restrict__ dstH, __nv_bfloat16* __restrict__ dstL)
{
    __shared__ __align__(16) __nv_bfloat16 sAh[128*RS], sAl[128*RS];
    __shared__ __align__(16) __nv_bfloat16 sWh[128*RS], sWl[128*RS];
    const int tid = threadIdx.x, lane = tid & 31, wid = tid >> 5;
    const int wm = wid >> 2, wn = wid & 3;
    const int m0 = blockIdx.y * 128, n0 = blockIdx.x * 128;

    float acc[4][4][4];
    #pragma unroll
    for (int f = 0; f < 4; f++)
        #pragma unroll
        for (int g = 0; g < 4; g++)
            #pragma unroll
            for (int e = 0; e < 4; e++) acc[f][g][e] = 0.f;

    const int arow  = (lane & 7) + ((lane >> 3) & 1) * 8;
    const int acolB = (lane >> 4) * 16;
    const int brow  = (lane & 7) + (lane >> 4) * 8;
    const int bcolB = ((lane >> 3) & 1) * 16;

    const uint32_t bAh = smem_u32(sAh), bAl = smem_u32(sAl);
    const uint32_t bWh = smem_u32(sWh), bWl = smem_u32(sWl);

    const int lr0 = tid >> 2;
    const int lq  = (tid & 3) * 8;

    for (int kc = 0; kc < HID_ / 32; kc++) {
        const int k0 = kc * 32;
        #pragma unroll
        for (int i = 0; i < 2; i++) {
            const int r = lr0 + i * 64;
            const int so = r * RS + lq;
            const size_t ga = (size_t)(m0 + r) * HID_ + k0 + lq;
            const size_t gw = (size_t)(n0 + r) * HID_ + k0 + lq;
            *(uint4*)&sAh[so] = *(const uint4*)(Ah + ga);
            *(uint4*)&sAl[so] = *(const uint4*)(Al + ga);
            *(uint4*)&sWh[so] = *(const uint4*)(Wh + gw);
            *(uint4*)&sWl[so] = *(const uint4*)(Wl + gw);
        }
        __syncthreads();

        #pragma unroll
        for (int ks = 0; ks < 2; ks++) {
            const int kB = ks * 32;
            uint32_t wh[4][2], wl[4][2];
            #pragma unroll
            for (int p = 0; p < 2; p++) {
                const uint32_t ro = (uint32_t)(wn*32 + p*16 + brow) * (RS*2) + kB + bcolB;
                ldsm_x4(wh[2*p][0], wh[2*p][1], wh[2*p+1][0], wh[2*p+1][1], bWh + ro);
                ldsm_x4(wl[2*p][0], wl[2*p][1], wl[2*p+1][0], wl[2*p+1][1], bWl + ro);
            }
            #pragma unroll
            for (int f = 0; f < 4; f++) {
                const uint32_t ro = (uint32_t)(wm*64 + f*16 + arow) * (RS*2) + kB + acolB;
                uint32_t ah[4], al[4];
                ldsm_x4(ah[0], ah[1], ah[2], ah[3], bAh + ro);
                ldsm_x4(al[0], al[1], al[2], al[3], bAl + ro);
                #pragma unroll
                for (int g = 0; g < 4; g++) {
                    mma_bf16(acc[f][g], ah, wh[g]);
                    mma_bf16(acc[f][g], ah, wl[g]);
                    mma_bf16(acc[f][g], al, wh[g]);
                }
            }
        }
        __syncthreads();
    }

    const int mr = lane >> 2, nc = (lane & 3) * 2;
    #pragma unroll
    for (int f = 0; f < 4; f++) {
        #pragma unroll
        for (int g = 0; g < 4; g++) {
            #pragma unroll
            for (int half = 0; half < 2; half++) {
                const int m = m0 + wm*64 + f*16 + mr + half*8;
                const int n = n0 + wn*32 + g*8 + nc;
                const float v0 = acc[f][g][half*2 + 0];
                const float v1 = acc[f][g][half*2 + 1];
                if (MODE == 0) {
                    const int b = m >> 11, s = m & (S_ - 1);
                    const int h = n >> 6,  d = n & 63;
                    const size_t idx = (((size_t)(b * NH_ + h)) * S_ + s) * HD_ + d;
                    __nv_bfloat16 h0 = __float2bfloat16_rn(v0);
                    __nv_bfloat16 h1 = __float2bfloat16_rn(v1);
                    __nv_bfloat16 l0 = __float2bfloat16_rn(v0 - __bfloat162float(h0));
                    __nv_bfloat16 l1 = __float2bfloat16_rn(v1 - __bfloat162float(h1));
                    *(__nv_bfloat162*)&dstH[idx] = __halves2bfloat162(h0, h1);
                    *(__nv_bfloat162*)&dstL[idx] = __halves2bfloat162(l0, l1);
                } else {
                    float* p = &dstF[(size_t)m * HID_ + n];
                    p[0] = v0 + bias[n];
                    p[1] = v1 + bias[n + 1];
                }
            }
        }
    }
}

// ---------------- tensor-core causal flash attention -------------------------
// grid (S/64, B*NH), 128 threads (4 warps). Warp w owns q rows [64qt+16w, +16).
// KV tiles of 32. Split-bf16 both MMAs. Softmax in registers (quad shfl).
// Output written as split bf16 directly into g_Ah/g_Al ([b*S+s][HID]).
#define QRS 72   // smem row stride (elems); 144B rows -> conflict-free ldmatrix

__global__ __launch_bounds__(128)
void attn_mma()
{
    __shared__ __align__(16) __nv_bfloat16 sQh[64*QRS], sQl[64*QRS];
    __shared__ __align__(16) __nv_bfloat16 sKh[32*QRS], sKl[32*QRS];
    __shared__ __align__(16) __nv_bfloat16 sVh[32*QRS], sVl[32*QRS];

    const int tid = threadIdx.x, lane = tid & 31, w = tid >> 5;
    const int qt = blockIdx.x, bh = blockIdx.y;
    const int q0 = qt * 64;
    const size_t base = (size_t)bh * S_ * HD_;

    // load Q tile (64 x 64 bf16, hi+lo): 512 uint4 per array
    for (int i = tid; i < 512; i += 128) {
        const int r = i >> 3, c8 = (i & 7) * 8;
        const size_t g = base + (size_t)(q0 + r) * HD_ + c8;
        *(uint4*)&sQh[r*QRS + c8] = *(const uint4*)(g_Qh + g);
        *(uint4*)&sQl[r*QRS + c8] = *(const uint4*)(g_Ql + g);
    }
    __syncthreads();

    const int arow  = (lane & 7) + ((lane >> 3) & 1) * 8;
    const int acolB = (lane >> 4) * 16;
    const int brow  = (lane & 7) + (lane >> 4) * 8;
    const int bcolB = ((lane >> 3) & 1) * 16;

    // Q A-frags (persistent)
    uint32_t qh[4][4], ql[4][4];
    {
        const uint32_t bQh = smem_u32(sQh), bQl = smem_u32(sQl);
        #pragma unroll
        for (int ks = 0; ks < 4; ks++) {
            const uint32_t ro = (uint32_t)(w*16 + arow) * (QRS*2) + ks*32 + acolB;
            ldsm_x4(qh[ks][0], qh[ks][1], qh[ks][2], qh[ks][3], bQh + ro);
            ldsm_x4(ql[ks][0], ql[ks][1], ql[ks][2], ql[ks][3], bQl + ro);
        }
    }

    const uint32_t bKh = smem_u32(sKh), bKl = smem_u32(sKl);
    const uint32_t bVh = smem_u32(sVh), bVl = smem_u32(sVl);

    float acc[8][4];
    #pragma unroll
    for (int nf = 0; nf < 8; nf++)
        #pragma unroll
        for (int e = 0; e < 4; e++) acc[nf][e] = 0.f;

    float mr0 = -1e30f, mr1 = -1e30f, l0 = 0.f, l1 = 0.f;
    const int qrow0 = q0 + w*16 + (lane >> 2);
    const int qrow1 = qrow0 + 8;

    const int nkt = 2*qt + 2;
    for (int kt = 0; kt < nkt; kt++) {
        const int k0 = kt * 32;
        // load K,V tiles (32 x 64, hi+lo)
        for (int i = tid; i < 256; i += 128) {
            const int r = i >> 3, c8 = (i & 7) * 8;
            const size_t g = base + (size_t)(k0 + r) * HD_ + c8;
            *(uint4*)&sKh[r*QRS + c8] = *(const uint4*)(g_Kh + g);
            *(uint4*)&sKl[r*QRS + c8] = *(const uint4*)(g_Kl + g);
            *(uint4*)&sVh[r*QRS + c8] = *(const uint4*)(g_Vh + g);
            *(uint4*)&sVl[r*QRS + c8] = *(const uint4*)(g_Vl + g);
        }
        __syncthreads();

        // S = Q K^T  (m16 x n32 per warp)
        float s[4][4];
        #pragma unroll
        for (int nf = 0; nf < 4; nf++)
            #pragma unroll
            for (int e = 0; e < 4; e++) s[nf][e] = 0.f;
        #pragma unroll
        for (int ks = 0; ks < 4; ks++) {
            #pragma unroll
            for (int g2 = 0; g2 < 2; g2++) {
                uint32_t kh[4], kl[4];
                const uint32_t ro = (uint32_t)(g2*16 + brow) * (QRS*2) + ks*32 + bcolB;
                ldsm_x4(kh[0], kh[1], kh[2], kh[3], bKh + ro);
                ldsm_x4(kl[0], kl[1], kl[2], kl[3], bKl + ro);
                mma_bf16(s[2*g2],   qh[ks], kh);
                mma_bf16(s[2*g2],   qh[ks], kl);
                mma_bf16(s[2*g2],   ql[ks], kh);
                mma_bf16(s[2*g2+1], qh[ks], kh+2);
                mma_bf16(s[2*g2+1], qh[ks], kl+2);
                mma_bf16(s[2*g2+1], ql[ks], kh+2);
            }
        }

        // scale to base-2 units + causal mask + row max
        float rx0 = -1e30f, rx1 = -1e30f;
        #pragma unroll
        for (int nf = 0; nf < 4; nf++) {
            const int kvb = k0 + nf*8 + (lane & 3)*2;
            #pragma unroll
            for (int c = 0; c < 4; c++) {
                float t = s[nf][c] * 0.18033688011f;     // (1/8)*log2(e)
                const int kv = kvb + (c & 1);
                const int qr = (c < 2) ? qrow0 : qrow1;
                if (kv > qr) t = -1e30f;
                s[nf][c] = t;
            }
            rx0 = fmaxf(rx0, fmaxf(s[nf][0], s[nf][1]));
            rx1 = fmaxf(rx1, fmaxf(s[nf][2], s[nf][3]));
        }
        rx0 = fmaxf(rx0, __shfl_xor_sync(0xffffffffu, rx0, 1));
        rx0 = fmaxf(rx0, __shfl_xor_sync(0xffffffffu, rx0, 2));
        rx1 = fmaxf(rx1, __shfl_xor_sync(0xffffffffu, rx1, 1));
        rx1 = fmaxf(rx1, __shfl_xor_sync(0xffffffffu, rx1, 2));
        const float mn0 = fmaxf(mr0, rx0), mn1 = fmaxf(mr1, rx1);
        const float a0 = exp2p(mr0 - mn0), a1 = exp2p(mr1 - mn1);
        mr0 = mn0; mr1 = mn1;

        // P = 2^(s-m): compute, sum, split+pack into PV A-frags
        float rs0 = 0.f, rs1 = 0.f;
        uint32_t pha[2][4], pla[2][4];
        #pragma unroll
        for (int nf = 0; nf < 4; nf++) {
            const float p0 = exp2p(s[nf][0] - mn0);
            const float p1 = exp2p(s[nf][1] - mn0);
            const float p2 = exp2p(s[nf][2] - mn1);
            const float p3 = exp2p(s[nf][3] - mn1);
            rs0 += p0 + p1; rs1 += p2 + p3;
            float q0r, q1r, q2r, q3r;
            pha[nf >> 1][(nf & 1)*2 + 0] = pack_hi(p0, p1, q0r, q1r);
            pha[nf >> 1][(nf & 1)*2 + 1] = pack_hi(p2, p3, q2r, q3r);
            pla[nf >> 1][(nf & 1)*2 + 0] = pack_bf(q0r, q1r);
            pla[nf >> 1][(nf & 1)*2 + 1] = pack_bf(q2r, q3r);
        }
        rs0 += __shfl_xor_sync(0xffffffffu, rs0, 1);
        rs0 += __shfl_xor_sync(0xffffffffu, rs0, 2);
        rs1 += __shfl_xor_sync(0xffffffffu, rs1, 1);
        rs1 += __shfl_xor_sync(0xffffffffu, rs1, 2);
        l0 = l0 * a0 + rs0;
        l1 = l1 * a1 + rs1;
        #pragma unroll
        for (int nf = 0; nf < 8; nf++) {
            acc[nf][0] *= a0; acc[nf][1] *= a0;
            acc[nf][2] *= a1; acc[nf][3] *= a1;
        }

        // O += P V  (V via ldmatrix.trans; split bf16)
        #pragma unroll
        for (int ks2 = 0; ks2 < 2; ks2++) {
            #pragma unroll
            for (int g2 = 0; g2 < 4; g2++) {
                uint32_t vh[4], vl[4];
                const uint32_t ro = (uint32_t)(ks2*16 + arow) * (QRS*2) + g2*32 + acolB;
                ldsm_x4_t(vh[0], vh[1], vh[2], vh[3], bVh + ro);
                ldsm_x4_t(vl[0], vl[1], vl[2], vl[3], bVl + ro);
                mma_bf16(acc[2*g2],   pha[ks2], vh);
                mma_bf16(acc[2*g2],   pha[ks2], vl);
                mma_bf16(acc[2*g2],   pla[ks2], vh);
                mma_bf16(acc[2*g2+1], pha[ks2], vh+2);
                mma_bf16(acc[2*g2+1], pha[ks2], vl+2);
                mma_bf16(acc[2*g2+1], pla[ks2], vh+2);
            }
        }
        __syncthreads();
    }

    // epilogue: O/l -> split bf16 straight into final-GEMM A buffers
    const float inv0 = 1.f / l0, inv1 = 1.f / l1;
    const int b = bh >> 4, h = bh & 15;
    const int row0 = q0 + w*16 + (lane >> 2), row1 = row0 + 8;
    const int dc = (lane & 3) * 2;
    #pragma unroll
    for (int nf = 0; nf < 8; nf++) {
        const int d = nf*8 + dc;
        const float o0 = acc[nf][0] * inv0, o1 = acc[nf][1] * inv0;
        const float o2 = acc[nf][2] * inv1, o3 = acc[nf][3] * inv1;
        const size_t i0 = ((size_t)(b * S_) + row0) * HID_ + h * HD_ + d;
        const size_t i1 = ((size_t)(b * S_) + row1) * HID_ + h * HD_ + d;
        float r0, r1, r2, r3;
        const uint32_t h01 = pack_hi(o0, o1, r0, r1);
        const uint32_t h23 = pack_hi(o2, o3, r2, r3);
        *(uint32_t*)&g_Ah[i0] = h01;
        *(uint32_t*)&g_Ah[i1] = h23;
        *(uint32_t*)&g_Al[i0] = pack_bf(r0, r1);
        *(uint32_t*)&g_Al[i1] = pack_bf(r2, r3);
    }
}

// ---------------- launch -----------------------------------------------------
extern "C" void kernel_launch(void* const* d_in, const int* in_sizes, int n_in,
                              void* d_out, int out_size)
{
    const float* query = (const float*)d_in[0];
    const float* key   = (const float*)d_in[1];
    const float* value = (const float*)d_in[2];
    // d_in[3] = mask: known causal tril, applied analytically in-kernel
    const float* Wq = (const float*)d_in[4];
    const float* Wk = (const float*)d_in[5];
    const float* Wv = (const float*)d_in[6];
    const float* Wo = (const float*)d_in[7];
    const float* bo = (const float*)d_in[8];
    float* out = (float*)d_out;

    __nv_bfloat16 *Ah, *Al, *Wh, *Wl, *Qh, *Ql, *Kh, *Kl, *Vh, *Vl;
    cudaGetSymbolAddress((void**)&Ah, g_Ah);
    cudaGetSymbolAddress((void**)&Al, g_Al);
    cudaGetSymbolAddress((void**)&Wh, g_Wh);
    cudaGetSymbolAddress((void**)&Wl, g_Wl);
    cudaGetSymbolAddress((void**)&Qh, g_Qh);
    cudaGetSymbolAddress((void**)&Ql, g_Ql);
    cudaGetSymbolAddress((void**)&Kh, g_Kh);
    cudaGetSymbolAddress((void**)&Kl, g_Kl);
    cudaGetSymbolAddress((void**)&Vh, g_Vh);
    cudaGetSymbolAddress((void**)&Vl, g_Vl);

    const int nA4 = M_ * HID_ / 4;
    const int nW4 = HID_ * HID_ / 4;
    dim3 gg(HID_/128, M_/128);   // (8, 32)

    split_f32<<<nA4/256, 256>>>((const float4*)query, Ah, Al, nA4);
    split_f32<<<nW4/256, 256>>>((const float4*)Wq, Wh, Wl, nW4);
    mma_gemm<0><<<gg, 256>>>(Ah, Al, Wh, Wl, nullptr, nullptr, Qh, Ql);

    split_f32<<<nA4/256, 256>>>((const float4*)key, Ah, Al, nA4);
    split_f32<<<nW4/256, 256>>>((const float4*)Wk, Wh, Wl, nW4);
    mma_gemm<0><<<gg, 256>>>(Ah, Al, Wh, Wl, nullptr, nullptr, Kh, Kl);

    split_f32<<<nA4/256, 256>>>((const float4*)value, Ah, Al, nA4);
    split_f32<<<nW4/256, 256>>>((const float4*)Wv, Wh, Wl, nW4);
    mma_gemm<0><<<gg, 256>>>(Ah, Al, Wh, Wl, nullptr, nullptr, Vh, Vl);

    attn_mma<<<dim3(S_/64, B_*NH_), 128>>>();   // writes split X into g_Ah/g_Al

    split_f32<<<nW4/256, 256>>>((const float4*)Wo, Wh, Wl, nW4);
    mma_gemm<1><<<gg, 256>>>(Ah, Al, Wh, Wl, bo, out, nullptr, nullptr);
}